// round 1
// baseline (speedup 1.0000x reference)
#include <cuda_runtime.h>

// -------------------------------------------------------------------------
// MaskedBilinearFullSymLoss — B=16, C=2, H=W=512, scalar f32 output.
//
// Positive branch (dx > 0):
//   delta_c = g_c(i,j) - bilerp(g_c; i+dy, j+dx)          (weights sum to 1)
//   err = delta_0*sym_y + delta_1*sym_x
//   loss += mask(i,j) * err^2  over { i < H-dy2, j < W-dx2 }, / ((H-dy2)(W-dx2))
//
// Negative branch (dx <= 0), simplified (second-term column identical for
// b=1,2; row/col weights each sum to 1):
//   delta_c = [wx1*g_c(i+dy2, j) + wx2*g_c(i+dy2, min(j+1,W-1))]
//           - [wy1*g_c(i+1, j-dx1) + wy2*g_c(i, j-dx1)]
//   loss += mask(i+dy2, j-dx1) * err^2 over { i < H-dy2, j < W+dx1 },
//           / ((H-dy2)(W+dx1))
//
// Final output = mean over batch. Accumulated in a __device__ double.
// -------------------------------------------------------------------------

#define HH 512
#define WW 512

__device__ double g_acc;

__global__ void zero_kernel() { g_acc = 0.0; }

__global__ void final_kernel(float* out) { out[0] = (float)g_acc; }

__global__ __launch_bounds__(256)
void loss_kernel(const float* __restrict__ grid,
                 const float* __restrict__ gt,
                 const float* __restrict__ gd,
                 const float* __restrict__ mask,
                 int B)
{
    const int H = HH, W = WW;
    const int b = blockIdx.y;
    const int i = blockIdx.x;          // one image row per block

    // per-batch scalars (uniform within block; tiny L1-cached loads)
    const float dx = -8.0f * gt[2 * b + 0];
    const float dy =  8.0f * gt[2 * b + 1];
    const float sym_x = gd[2 * b + 0];
    const float sym_y = gd[2 * b + 1];

    const float dx1f = floorf(dx), dy1f = floorf(dy);
    const int dx1 = (int)dx1f, dy1 = (int)dy1f;
    const int dx2 = dx1 + 1,  dy2 = dy1 + 1;
    const float wx1 = (dx1f + 1.0f) - dx, wx2 = dx - dx1f;
    const float wy1 = (dy1f + 1.0f) - dy, wy2 = dy - dy1f;

    const float* __restrict__ g0 = grid + (size_t)(2 * b + 0) * H * W;
    const float* __restrict__ g1 = grid + (size_t)(2 * b + 1) * H * W;
    const float* __restrict__ mk = mask + (size_t)b * H * W;

    float acc = 0.0f;
    float cnt;

    if (dx > 0.0f) {
        cnt = (float)(H - dy2) * (float)(W - dx2);
        if (i < H - dy2) {
            const float* __restrict__ g0r = g0 + (size_t)i * W;
            const float* __restrict__ g1r = g1 + (size_t)i * W;
            const float* __restrict__ g0a = g0 + (size_t)(i + dy1) * W;
            const float* __restrict__ g0b = g0 + (size_t)(i + dy2) * W;
            const float* __restrict__ g1a = g1 + (size_t)(i + dy1) * W;
            const float* __restrict__ g1b = g1 + (size_t)(i + dy2) * W;
            const float* __restrict__ mr  = mk + (size_t)i * W;
            const int jmax = W - dx2;
            for (int j = threadIdx.x; j < jmax; j += blockDim.x) {
                // all sample indices in-range when valid (dy1,dx1 >= 0 here)
                float s0 = wy1 * (wx1 * g0a[j + dx1] + wx2 * g0a[j + dx2])
                         + wy2 * (wx1 * g0b[j + dx1] + wx2 * g0b[j + dx2]);
                float s1 = wy1 * (wx1 * g1a[j + dx1] + wx2 * g1a[j + dx2])
                         + wy2 * (wx1 * g1b[j + dx1] + wx2 * g1b[j + dx2]);
                float d0 = g0r[j] - s0;
                float d1 = g1r[j] - s1;
                float err = d0 * sym_y + d1 * sym_x;
                acc += mr[j] * err * err;
            }
        }
    } else {
        cnt = (float)(H - dy2) * (float)(W + dx1);
        if (i < H - dy2) {
            const float* __restrict__ g0A  = g0 + (size_t)(i + dy2) * W;
            const float* __restrict__ g1A  = g1 + (size_t)(i + dy2) * W;
            const float* __restrict__ g0s1 = g0 + (size_t)(i + 1) * W;   // wy1
            const float* __restrict__ g0s2 = g0 + (size_t)i * W;         // wy2
            const float* __restrict__ g1s1 = g1 + (size_t)(i + 1) * W;
            const float* __restrict__ g1s2 = g1 + (size_t)i * W;
            const float* __restrict__ mA   = mk + (size_t)(i + dy2) * W;
            const int jmax = W + dx1;      // dx1 <= 0
            for (int j = threadIdx.x; j < jmax; j += blockDim.x) {
                const int cB = j - dx1;                  // <= W-1 (valid range)
                const int c1 = min(j + 1, W - 1);        // clamp for dx1 == 0
                float f0 = wx1 * g0A[j] + wx2 * g0A[c1];
                float f1 = wx1 * g1A[j] + wx2 * g1A[c1];
                float s0 = wy1 * g0s1[cB] + wy2 * g0s2[cB];
                float s1 = wy1 * g1s1[cB] + wy2 * g1s2[cB];
                float d0 = f0 - s0;
                float d1 = f1 - s1;
                float err = d0 * sym_y + d1 * sym_x;
                acc += mA[cB] * err * err;
            }
        }
    }

    // ---- block reduction: warp shuffle, then shared, one atomic per block
    #pragma unroll
    for (int o = 16; o > 0; o >>= 1)
        acc += __shfl_down_sync(0xFFFFFFFFu, acc, o);

    __shared__ float wsum[8];
    const int lane = threadIdx.x & 31;
    const int warp = threadIdx.x >> 5;
    if (lane == 0) wsum[warp] = acc;
    __syncthreads();

    if (threadIdx.x == 0) {
        float s = 0.0f;
        #pragma unroll
        for (int k = 0; k < 8; k++) s += wsum[k];
        // fold per-batch 1/cnt and 1/B into the contribution
        double scaled = (double)s / ((double)cnt * (double)B);
        atomicAdd(&g_acc, scaled);
    }
}

extern "C" void kernel_launch(void* const* d_in, const int* in_sizes, int n_in,
                              void* d_out, int out_size)
{
    const float* grid = (const float*)d_in[0];
    const float* gt   = (const float*)d_in[1];
    const float* gd   = (const float*)d_in[2];
    const float* mask = (const float*)d_in[3];
    float* out = (float*)d_out;

    const int B = in_sizes[1] / 2;   // gt_sym_axis is (B, 2)

    zero_kernel<<<1, 1>>>();
    dim3 g(HH, B);
    loss_kernel<<<g, 256>>>(grid, gt, gd, mask, B);
    final_kernel<<<1, 1>>>(out);
}

// round 2
// speedup vs baseline: 1.0986x; 1.0986x over previous
#include <cuda_runtime.h>

// -------------------------------------------------------------------------
// MaskedBilinearFullSymLoss — B=16, C=2, H=W=512, scalar f32 output.
// Single fused kernel: per-block partial sums -> fp64 atomic accumulator ->
// last block (atomicInc ticket, auto-wrap) writes d_out and resets state.
// -------------------------------------------------------------------------

#define HH 512
#define WW 512
#define RPB 4              // rows per block
#define NBLK ((HH / RPB) * 16)   // total blocks for B=16 (recomputed at runtime)

__device__ double g_acc;            // zero-initialized
__device__ unsigned int g_ticket;   // zero-initialized

__global__ __launch_bounds__(256)
void loss_kernel(const float* __restrict__ grid,
                 const float* __restrict__ gt,
                 const float* __restrict__ gd,
                 const float* __restrict__ mask,
                 int B, unsigned int nblocks, float* __restrict__ out)
{
    const int H = HH, W = WW;
    const int b  = blockIdx.y;
    const int i0 = blockIdx.x * RPB;   // first image row handled by this block

    // per-batch scalars (uniform within block; L1-cached)
    const float dx = -8.0f * gt[2 * b + 0];
    const float dy =  8.0f * gt[2 * b + 1];
    const float sym_x = gd[2 * b + 0];
    const float sym_y = gd[2 * b + 1];

    const float dx1f = floorf(dx), dy1f = floorf(dy);
    const int dx1 = (int)dx1f, dy1 = (int)dy1f;
    const int dx2 = dx1 + 1,  dy2 = dy1 + 1;
    const float wx1 = (dx1f + 1.0f) - dx, wx2 = dx - dx1f;
    const float wy1 = (dy1f + 1.0f) - dy, wy2 = dy - dy1f;

    const float* __restrict__ g0 = grid + (size_t)(2 * b + 0) * H * W;
    const float* __restrict__ g1 = grid + (size_t)(2 * b + 1) * H * W;
    const float* __restrict__ mk = mask + (size_t)b * H * W;

    const int imax = H - dy2;         // valid row bound (same for both branches)
    float acc = 0.0f;
    float cnt;

    if (dx > 0.0f) {
        cnt = (float)imax * (float)(W - dx2);
        const int jmax = W - dx2;
        #pragma unroll
        for (int r = 0; r < RPB; r++) {
            const int i = i0 + r;
            if (i >= imax) break;
            const float* __restrict__ g0r = g0 + (size_t)i * W;
            const float* __restrict__ g1r = g1 + (size_t)i * W;
            const float* __restrict__ g0a = g0 + (size_t)(i + dy1) * W;
            const float* __restrict__ g0b = g0 + (size_t)(i + dy2) * W;
            const float* __restrict__ g1a = g1 + (size_t)(i + dy1) * W;
            const float* __restrict__ g1b = g1 + (size_t)(i + dy2) * W;
            const float* __restrict__ mr  = mk + (size_t)i * W;
            for (int j = threadIdx.x; j < jmax; j += 256) {
                float s0 = wy1 * (wx1 * g0a[j + dx1] + wx2 * g0a[j + dx2])
                         + wy2 * (wx1 * g0b[j + dx1] + wx2 * g0b[j + dx2]);
                float s1 = wy1 * (wx1 * g1a[j + dx1] + wx2 * g1a[j + dx2])
                         + wy2 * (wx1 * g1b[j + dx1] + wx2 * g1b[j + dx2]);
                float d0 = g0r[j] - s0;
                float d1 = g1r[j] - s1;
                float err = d0 * sym_y + d1 * sym_x;
                acc += mr[j] * err * err;
            }
        }
    } else {
        cnt = (float)imax * (float)(W + dx1);
        const int jmax = W + dx1;     // dx1 <= 0
        #pragma unroll
        for (int r = 0; r < RPB; r++) {
            const int i = i0 + r;
            if (i >= imax) break;
            const float* __restrict__ g0A  = g0 + (size_t)(i + dy2) * W;
            const float* __restrict__ g1A  = g1 + (size_t)(i + dy2) * W;
            const float* __restrict__ g0s1 = g0 + (size_t)(i + 1) * W;   // wy1
            const float* __restrict__ g0s2 = g0 + (size_t)i * W;         // wy2
            const float* __restrict__ g1s1 = g1 + (size_t)(i + 1) * W;
            const float* __restrict__ g1s2 = g1 + (size_t)i * W;
            const float* __restrict__ mA   = mk + (size_t)(i + dy2) * W;
            for (int j = threadIdx.x; j < jmax; j += 256) {
                const int cB = j - dx1;                  // <= W-1
                const int c1 = min(j + 1, W - 1);        // clamp for dx1 == 0
                float f0 = wx1 * g0A[j] + wx2 * g0A[c1];
                float f1 = wx1 * g1A[j] + wx2 * g1A[c1];
                float s0 = wy1 * g0s1[cB] + wy2 * g0s2[cB];
                float s1 = wy1 * g1s1[cB] + wy2 * g1s2[cB];
                float d0 = f0 - s0;
                float d1 = f1 - s1;
                float err = d0 * sym_y + d1 * sym_x;
                acc += mA[cB] * err * err;
            }
        }
    }

    // ---- block reduction
    #pragma unroll
    for (int o = 16; o > 0; o >>= 1)
        acc += __shfl_down_sync(0xFFFFFFFFu, acc, o);

    __shared__ float wsum[8];
    const int lane = threadIdx.x & 31;
    const int warp = threadIdx.x >> 5;
    if (lane == 0) wsum[warp] = acc;
    __syncthreads();

    if (threadIdx.x == 0) {
        float s = 0.0f;
        #pragma unroll
        for (int k = 0; k < 8; k++) s += wsum[k];
        double scaled = (double)s / ((double)cnt * (double)B);
        atomicAdd(&g_acc, scaled);

        __threadfence();
        // ticket with auto-wrap: old == nblocks-1 -> counter resets to 0
        unsigned int prev = atomicInc(&g_ticket, nblocks - 1u);
        if (prev == nblocks - 1u) {
            // all other blocks' g_acc adds are visible (fence + atomic order)
            double total = atomicAdd(&g_acc, 0.0);   // atomic read
            out[0] = (float)total;
            g_acc = 0.0;                              // reset for next replay
            __threadfence();
        }
    }
}

extern "C" void kernel_launch(void* const* d_in, const int* in_sizes, int n_in,
                              void* d_out, int out_size)
{
    const float* grid = (const float*)d_in[0];
    const float* gt   = (const float*)d_in[1];
    const float* gd   = (const float*)d_in[2];
    const float* mask = (const float*)d_in[3];
    float* out = (float*)d_out;

    const int B = in_sizes[1] / 2;   // gt_sym_axis is (B, 2)

    dim3 g(HH / RPB, B);
    unsigned int nblocks = (HH / RPB) * B;
    loss_kernel<<<g, 256>>>(grid, gt, gd, mask, B, nblocks, out);
}

// round 3
// speedup vs baseline: 1.3361x; 1.2162x over previous
#include <cuda_runtime.h>

// -------------------------------------------------------------------------
// MaskedBilinearFullSymLoss — B=16, C=2, H=W=512, scalar f32 output.
// Single fused kernel, latency-optimized: 8 pixels per thread straight-line
// (4 rows x 2 cols), loads batched before compute for high MLP.
// -------------------------------------------------------------------------

#define HH 512
#define WW 512
#define RPB 4                     // rows per block

__device__ double g_acc;          // zero-initialized
__device__ unsigned int g_ticket; // zero-initialized

__global__ __launch_bounds__(256, 4)
void loss_kernel(const float* __restrict__ grid,
                 const float* __restrict__ gt,
                 const float* __restrict__ gd,
                 const float* __restrict__ mask,
                 int B, unsigned int nblocks, float* __restrict__ out)
{
    const int H = HH, W = WW;
    const int b  = blockIdx.y;
    const int i0 = blockIdx.x * RPB;

    const float dx = -8.0f * gt[2 * b + 0];
    const float dy =  8.0f * gt[2 * b + 1];
    const float sym_x = gd[2 * b + 0];
    const float sym_y = gd[2 * b + 1];

    const float dx1f = floorf(dx), dy1f = floorf(dy);
    const int dx1 = (int)dx1f, dy1 = (int)dy1f;
    const int dx2 = dx1 + 1,  dy2 = dy1 + 1;
    const float wx1 = (dx1f + 1.0f) - dx, wx2 = dx - dx1f;
    const float wy1 = (dy1f + 1.0f) - dy, wy2 = dy - dy1f;
    // bilinear corner weights (positive branch)
    const float w11 = wy1 * wx1, w12 = wy1 * wx2;
    const float w21 = wy2 * wx1, w22 = wy2 * wx2;

    const float* __restrict__ g0 = grid + (size_t)(2 * b + 0) * H * W;
    const float* __restrict__ g1 = grid + (size_t)(2 * b + 1) * H * W;
    const float* __restrict__ mk = mask + (size_t)b * H * W;

    const int imax = H - dy2;
    const int tid  = threadIdx.x;
    float acc = 0.0f;
    float cnt;

    if (dx > 0.0f) {
        const int jmax = W - dx2;
        cnt = (float)imax * (float)jmax;
        #pragma unroll
        for (int r = 0; r < RPB; r++) {
            const int i = i0 + r;
            if (i >= imax) break;
            const float* __restrict__ g0r = g0 + (size_t)i * W;
            const float* __restrict__ g1r = g1 + (size_t)i * W;
            const float* __restrict__ g0a = g0 + (size_t)(i + dy1) * W + dx1;
            const float* __restrict__ g0b = g0 + (size_t)(i + dy2) * W + dx1;
            const float* __restrict__ g1a = g1 + (size_t)(i + dy1) * W + dx1;
            const float* __restrict__ g1b = g1 + (size_t)(i + dy2) * W + dx1;
            const float* __restrict__ mr  = mk + (size_t)i * W;
            #pragma unroll
            for (int jj = 0; jj < 2; jj++) {
                const int j = tid + jj * 256;
                if (jj == 0 || j < jmax) {
                    // batch all 11 loads first
                    float a1 = g0a[j],     a2 = g0a[j + 1];
                    float b1 = g0b[j],     b2 = g0b[j + 1];
                    float c1 = g1a[j],     c2 = g1a[j + 1];
                    float e1 = g1b[j],     e2 = g1b[j + 1];
                    float r0 = g0r[j],     r1 = g1r[j];
                    float mm = mr[j];
                    float s0 = w11 * a1 + w12 * a2 + w21 * b1 + w22 * b2;
                    float s1 = w11 * c1 + w12 * c2 + w21 * e1 + w22 * e2;
                    float err = (r0 - s0) * sym_y + (r1 - s1) * sym_x;
                    acc += mm * err * err;
                }
            }
        }
    } else {
        const int jmax = W + dx1;         // dx1 <= 0
        cnt = (float)imax * (float)jmax;
        #pragma unroll
        for (int r = 0; r < RPB; r++) {
            const int i = i0 + r;
            if (i >= imax) break;
            const float* __restrict__ g0A  = g0 + (size_t)(i + dy2) * W;
            const float* __restrict__ g1A  = g1 + (size_t)(i + dy2) * W;
            const float* __restrict__ g0s1 = g0 + (size_t)(i + 1) * W - dx1;
            const float* __restrict__ g0s2 = g0 + (size_t)i * W - dx1;
            const float* __restrict__ g1s1 = g1 + (size_t)(i + 1) * W - dx1;
            const float* __restrict__ g1s2 = g1 + (size_t)i * W - dx1;
            const float* __restrict__ mA   = mk + (size_t)(i + dy2) * W - dx1;
            #pragma unroll
            for (int jj = 0; jj < 2; jj++) {
                const int j = tid + jj * 256;
                if (jj == 0 || j < jmax) {
                    const int c1 = min(j + 1, W - 1);   // clamp when dx1 == 0
                    float a1 = g0A[j],  a2 = g0A[c1];
                    float b1 = g1A[j],  b2 = g1A[c1];
                    float p1 = g0s1[j], p2 = g0s2[j];
                    float q1 = g1s1[j], q2 = g1s2[j];
                    float mm = mA[j];
                    float f0 = wx1 * a1 + wx2 * a2;
                    float f1 = wx1 * b1 + wx2 * b2;
                    float s0 = wy1 * p1 + wy2 * p2;
                    float s1 = wy1 * q1 + wy2 * q2;
                    float err = (f0 - s0) * sym_y + (f1 - s1) * sym_x;
                    acc += mm * err * err;
                }
            }
        }
    }

    // ---- block reduction
    #pragma unroll
    for (int o = 16; o > 0; o >>= 1)
        acc += __shfl_down_sync(0xFFFFFFFFu, acc, o);

    __shared__ float wsum[8];
    const int lane = tid & 31;
    const int warp = tid >> 5;
    if (lane == 0) wsum[warp] = acc;
    __syncthreads();

    if (tid == 0) {
        float s = 0.0f;
        #pragma unroll
        for (int k = 0; k < 8; k++) s += wsum[k];
        double scaled = (double)s / ((double)cnt * (double)B);
        atomicAdd(&g_acc, scaled);

        __threadfence();
        unsigned int prev = atomicInc(&g_ticket, nblocks - 1u);
        if (prev == nblocks - 1u) {
            double total = atomicAdd(&g_acc, 0.0);   // atomic read
            out[0] = (float)total;
            g_acc = 0.0;                              // reset for next replay
            __threadfence();
        }
    }
}

extern "C" void kernel_launch(void* const* d_in, const int* in_sizes, int n_in,
                              void* d_out, int out_size)
{
    const float* grid = (const float*)d_in[0];
    const float* gt   = (const float*)d_in[1];
    const float* gd   = (const float*)d_in[2];
    const float* mask = (const float*)d_in[3];
    float* out = (float*)d_out;

    const int B = in_sizes[1] / 2;   // gt_sym_axis is (B, 2)

    dim3 g(HH / RPB, B);
    unsigned int nblocks = (HH / RPB) * B;
    loss_kernel<<<g, 256>>>(grid, gt, gd, mask, B, nblocks, out);
}